// round 1
// baseline (speedup 1.0000x reference)
#include <cuda_runtime.h>
#include <math.h>

#define N_NODES_MAX 50000
#define N_EDGES_MAX 800000
#define IN_CH 128
#define HID 64

// Scratch (allocation-free rule: __device__ globals)
__device__ float g_deg[N_NODES_MAX];                 // degree, then dinv in-place
__device__ float g_h[N_NODES_MAX * HID];             // GEMM output (reused both layers)
__device__ float g_agg1[N_NODES_MAX * HID];          // layer-1 aggregation -> z1
__device__ float g_agg2[N_NODES_MAX * HID];          // layer-2 aggregation -> z2

// ---------------------------------------------------------------------------
// init: deg = 1 (self-loop), agg1 = agg2 = 0
__global__ void init_kernel(int n) {
    int i = blockIdx.x * blockDim.x + threadIdx.x;
    int total = n * HID;
    if (i < total) {
        g_agg1[i] = 0.f;
        g_agg2[i] = 0.f;
        if (i < n) g_deg[i] = 1.0f;
    }
}

// degree: count dst occurrences
__global__ void degree_kernel(const int* __restrict__ dst, int e) {
    int i = blockIdx.x * blockDim.x + threadIdx.x;
    if (i < e) atomicAdd(&g_deg[dst[i]], 1.0f);
}

// dinv = rsqrt(deg) in place
__global__ void dinv_kernel(int n) {
    int i = blockIdx.x * blockDim.x + threadIdx.x;
    if (i < n) g_deg[i] = rsqrtf(g_deg[i]);
}

// ---------------------------------------------------------------------------
// simple GEMM: H[n, HID] = X[n, K] @ W[K, HID]; W cached in smem.
// 256 threads: 4 nodes x 64 cols per block.
template <int K>
__global__ void gemm_kernel(const float* __restrict__ X, const float* __restrict__ W,
                            float* __restrict__ H, int n) {
    __shared__ float Ws[K * HID];
    __shared__ float Xs[4][K];
    int t = threadIdx.x;
    for (int i = t; i < K * HID; i += 256) Ws[i] = W[i];
    int node0 = blockIdx.x * 4;
    for (int i = t; i < 4 * K; i += 256) {
        int r = i / K, c = i % K;
        int node = node0 + r;
        Xs[r][c] = (node < n) ? X[node * K + c] : 0.f;
    }
    __syncthreads();
    int r = t >> 6;           // t / 64
    int c = t & 63;           // t % 64
    int node = node0 + r;
    if (node < n) {
        float acc = 0.f;
#pragma unroll
        for (int k = 0; k < K; ++k) acc += Xs[r][k] * Ws[k * HID + c];
        H[node * HID + c] = acc;
    }
}

// ---------------------------------------------------------------------------
// aggregation: one warp per (edge or self-loop). agg[dst] += h[src]*norm
__global__ void agg_kernel(const int* __restrict__ src, const int* __restrict__ dst,
                           const float* __restrict__ h, float* __restrict__ agg,
                           int e, int n) {
    int gw = (blockIdx.x * blockDim.x + threadIdx.x) >> 5;
    int lane = threadIdx.x & 31;
    int total = e + n;
    if (gw >= total) return;
    int s, d; float w;
    if (gw < e) {
        s = __ldg(src + gw);
        d = __ldg(dst + gw);
        w = g_deg[s] * g_deg[d];
    } else {
        s = d = gw - e;
        float di = g_deg[s];
        w = di * di;
    }
    float2 v = *(const float2*)(h + s * HID + lane * 2);
    float* out = agg + d * HID + lane * 2;
    atomicAdd(out,     v.x * w);
    atomicAdd(out + 1, v.y * w);
}

// bias (+optional relu) in place
__global__ void bias_act_kernel(float* __restrict__ a, const float* __restrict__ b,
                                int n, int relu) {
    int i = blockIdx.x * blockDim.x + threadIdx.x;
    if (i < n * HID) {
        float v = a[i] + __ldg(b + (i & (HID - 1)));
        a[i] = relu ? fmaxf(v, 0.f) : v;
    }
}

// ---------------------------------------------------------------------------
// decode: out[e] = dot(z[src], z[dst]) over HID. One warp per edge.
__global__ void decode_kernel(const int* __restrict__ src, const int* __restrict__ dst,
                              const float* __restrict__ z, float* __restrict__ out, int e) {
    int gw = (blockIdx.x * blockDim.x + threadIdx.x) >> 5;
    int lane = threadIdx.x & 31;
    if (gw >= e) return;
    int s = __ldg(src + gw), d = __ldg(dst + gw);
    float2 a  = *(const float2*)(z + s * HID + lane * 2);
    float2 bv = *(const float2*)(z + d * HID + lane * 2);
    float p = a.x * bv.x + a.y * bv.y;
#pragma unroll
    for (int o = 16; o; o >>= 1) p += __shfl_xor_sync(0xffffffffu, p, o);
    if (lane == 0) out[gw] = p;
}

// ---------------------------------------------------------------------------
extern "C" void kernel_launch(void* const* d_in, const int* in_sizes, int n_in,
                              void* d_out, int out_size) {
    const float* x   = (const float*)d_in[0];   // [n, IN_CH]
    const int*   ei  = (const int*)d_in[1];     // [2, e]
    const float* W1  = (const float*)d_in[2];   // [IN_CH, HID]
    const float* b1  = (const float*)d_in[3];   // [HID]
    const float* W2  = (const float*)d_in[4];   // [HID, HID]
    const float* b2  = (const float*)d_in[5];   // [HID]
    float* out = (float*)d_out;                 // [e]

    int n = in_sizes[0] / IN_CH;
    int e = in_sizes[1] / 2;
    const int* src = ei;
    const int* dst = ei + e;

    // device pointers for scratch
    float *p_h, *p_agg1, *p_agg2;
    cudaGetSymbolAddress((void**)&p_h, g_h);
    cudaGetSymbolAddress((void**)&p_agg1, g_agg1);
    cudaGetSymbolAddress((void**)&p_agg2, g_agg2);

    const int T = 256;

    // 1. init
    init_kernel<<<(n * HID + T - 1) / T, T>>>(n);
    // 2. degree
    degree_kernel<<<(e + T - 1) / T, T>>>(dst, e);
    // 3. dinv
    dinv_kernel<<<(n + T - 1) / T, T>>>(n);
    // 4. layer-1 GEMM
    gemm_kernel<IN_CH><<<(n + 3) / 4, T>>>(x, W1, p_h, n);
    // 5. layer-1 aggregation (edges + self-loops), one warp per edge
    {
        long long warps = (long long)e + n;
        long long blocks = (warps * 32 + T - 1) / T;
        agg_kernel<<<(int)blocks, T>>>(src, dst, p_h, p_agg1, e, n);
    }
    // 6. bias + relu -> z1 (in agg1)
    bias_act_kernel<<<(n * HID + T - 1) / T, T>>>(p_agg1, b1, n, 1);
    // 7. layer-2 GEMM
    gemm_kernel<HID><<<(n + 3) / 4, T>>>(p_agg1, W2, p_h, n);
    // 8. layer-2 aggregation
    {
        long long warps = (long long)e + n;
        long long blocks = (warps * 32 + T - 1) / T;
        agg_kernel<<<(int)blocks, T>>>(src, dst, p_h, p_agg2, e, n);
    }
    // 9. bias -> z2 (in agg2)
    bias_act_kernel<<<(n * HID + T - 1) / T, T>>>(p_agg2, b2, n, 0);
    // 10. decode
    {
        long long warps = e;
        long long blocks = (warps * 32 + T - 1) / T;
        decode_kernel<<<(int)blocks, T>>>(src, dst, p_agg2, out, e);
    }
}

// round 2
// speedup vs baseline: 1.3941x; 1.3941x over previous
#include <cuda_runtime.h>
#include <math.h>

#define IN_CH 128
#define HID 64
#define NMAX 50000
#define EMAX 800000

// Scratch (__device__ globals; no allocation allowed)
__device__ float g_deg[NMAX];              // degree, then dinv in place
__device__ float g_h[NMAX * HID];          // h' = (X@W) * dinv[row]  (gather source)
__device__ float g_agg1[NMAX * HID];       // layer-1 aggregation (init = h' via dual-store)
__device__ float g_agg2[NMAX * HID];       // layer-2 aggregation

// ---------------------------------------------------------------------------
__global__ void init_deg_kernel(int n) {
    int i = blockIdx.x * blockDim.x + threadIdx.x;
    if (i < n) g_deg[i] = 1.0f;            // self-loop contributes 1
}

__global__ void degree_kernel(const int* __restrict__ dst, int e) {
    int i = blockIdx.x * blockDim.x + threadIdx.x;
    if (i < e) {
        float* p = &g_deg[__ldg(dst + i)];
        asm volatile("red.global.add.f32 [%0], %1;" :: "l"(p), "f"(1.0f) : "memory");
    }
}

__global__ void dinv_kernel(int n) {
    int i = blockIdx.x * blockDim.x + threadIdx.x;
    if (i < n) g_deg[i] = rsqrtf(g_deg[i]);
}

// ---------------------------------------------------------------------------
// GEMM: out[i][c] = dinv[i] * sum_k in[i][k] * W[k][c], dual-stored to H and AGG.
// TRANS: input transform z = relu(dinv[i]*in[i][k] + bIn[k])  (layer-2 input path)
// Block: 256 threads = 32 nodes x 8 col-groups; each thread computes 8 contiguous cols
// with fma.rn.f32x2 packed math (2 fp32 FMA per instruction).
template <int K, bool TRANS>
__global__ void gemm_kernel(const float* __restrict__ X, const float* __restrict__ W,
                            const float* __restrict__ bIn,
                            float* __restrict__ H, float* __restrict__ AGG, int n) {
    constexpr int XP = K + 4;              // pad to kill smem bank conflicts
    __shared__ float Ws[K * HID];
    __shared__ float Xs[32 * XP];
    const int t = threadIdx.x;
    const int node0 = blockIdx.x * 32;

    // load W [K,HID] (coalesced float4)
    for (int i = t * 4; i < K * HID; i += 1024)
        *(float4*)(Ws + i) = *(const float4*)(W + i);

    // load X tile (optionally transformed)
    for (int i = t * 4; i < 32 * K; i += 1024) {
        int r = i / K, c = i % K;          // c is a multiple of 4
        int node = node0 + r;
        float4 v = make_float4(0.f, 0.f, 0.f, 0.f);
        if (node < n) {
            v = *(const float4*)(X + (size_t)node * K + c);
            if (TRANS) {
                float di = g_deg[node];
                float4 b = *(const float4*)(bIn + c);
                v.x = fmaxf(fmaf(di, v.x, b.x), 0.f);
                v.y = fmaxf(fmaf(di, v.y, b.y), 0.f);
                v.z = fmaxf(fmaf(di, v.z, b.z), 0.f);
                v.w = fmaxf(fmaf(di, v.w, b.w), 0.f);
            }
        }
        *(float4*)(Xs + r * XP + c) = v;
    }
    __syncthreads();

    const int nl = t >> 3;                 // local node 0..31
    const int c0 = (t & 7) * 8;            // 8 contiguous output cols
    unsigned long long a0 = 0, a1 = 0, a2 = 0, a3 = 0;   // 4x f32x2 accumulators
    const float* xrow = Xs + nl * XP;

#pragma unroll 8
    for (int k = 0; k < K; ++k) {
        float xv = xrow[k];
        unsigned long long xx;
        asm("mov.b64 %0, {%1, %1};" : "=l"(xx) : "f"(xv));
        ulonglong2 wA = *(const ulonglong2*)(Ws + k * HID + c0);
        ulonglong2 wB = *(const ulonglong2*)(Ws + k * HID + c0 + 4);
        asm("fma.rn.f32x2 %0, %1, %2, %0;" : "+l"(a0) : "l"(wA.x), "l"(xx));
        asm("fma.rn.f32x2 %0, %1, %2, %0;" : "+l"(a1) : "l"(wA.y), "l"(xx));
        asm("fma.rn.f32x2 %0, %1, %2, %0;" : "+l"(a2) : "l"(wB.x), "l"(xx));
        asm("fma.rn.f32x2 %0, %1, %2, %0;" : "+l"(a3) : "l"(wB.y), "l"(xx));
    }

    int node = node0 + nl;
    if (node < n) {
        float di = g_deg[node];
        float o[8];
        asm("mov.b64 {%0,%1}, %2;" : "=f"(o[0]), "=f"(o[1]) : "l"(a0));
        asm("mov.b64 {%0,%1}, %2;" : "=f"(o[2]), "=f"(o[3]) : "l"(a1));
        asm("mov.b64 {%0,%1}, %2;" : "=f"(o[4]), "=f"(o[5]) : "l"(a2));
        asm("mov.b64 {%0,%1}, %2;" : "=f"(o[6]), "=f"(o[7]) : "l"(a3));
        float4 r0 = make_float4(o[0] * di, o[1] * di, o[2] * di, o[3] * di);
        float4 r1 = make_float4(o[4] * di, o[5] * di, o[6] * di, o[7] * di);
        size_t off = (size_t)node * HID + c0;
        *(float4*)(H + off) = r0;
        *(float4*)(H + off + 4) = r1;
        *(float4*)(AGG + off) = r0;        // self-loop init: agg starts at h'[node]
        *(float4*)(AGG + off + 4) = r1;
    }
}

// ---------------------------------------------------------------------------
// aggregation: agg[dst] += h'[src]  (unweighted; norm folded into producer/consumer)
// 16 lanes per edge, one red.global.add.v4.f32 per lane.
__global__ void agg_kernel(const int* __restrict__ src, const int* __restrict__ dst,
                           const float* __restrict__ h, float* __restrict__ agg, int e) {
    int tid = blockIdx.x * blockDim.x + threadIdx.x;
    int edge = tid >> 4;
    int q = tid & 15;
    if (edge >= e) return;
    int s = __ldg(src + edge);
    int d = __ldg(dst + edge);
    float4 v = *(const float4*)(h + (size_t)s * HID + q * 4);
    float* p = agg + (size_t)d * HID + q * 4;
    asm volatile("red.global.add.v4.f32 [%0], {%1,%2,%3,%4};"
                 :: "l"(p), "f"(v.x), "f"(v.y), "f"(v.z), "f"(v.w) : "memory");
}

// ---------------------------------------------------------------------------
// decode: out[e] = dot(z[src], z[dst]), z = dinv*agg2 + b2 applied on the fly.
// 16 lanes per edge, float4 per lane, shfl-xor reduce within the 16-lane group.
__global__ void decode_kernel(const int* __restrict__ src, const int* __restrict__ dst,
                              const float* __restrict__ agg, const float* __restrict__ b,
                              float* __restrict__ out, int e) {
    int tid = blockIdx.x * blockDim.x + threadIdx.x;
    int edge = tid >> 4;
    int q = tid & 15;
    if (edge >= e) return;
    int s = __ldg(src + edge);
    int d = __ldg(dst + edge);
    float ds = g_deg[s], dd = g_deg[d];
    float4 as = *(const float4*)(agg + (size_t)s * HID + q * 4);
    float4 ad = *(const float4*)(agg + (size_t)d * HID + q * 4);
    float4 bb = *(const float4*)(b + q * 4);
    float p;
    {
        float zs = fmaf(ds, as.x, bb.x), zd = fmaf(dd, ad.x, bb.x);
        p = zs * zd;
        zs = fmaf(ds, as.y, bb.y); zd = fmaf(dd, ad.y, bb.y); p = fmaf(zs, zd, p);
        zs = fmaf(ds, as.z, bb.z); zd = fmaf(dd, ad.z, bb.z); p = fmaf(zs, zd, p);
        zs = fmaf(ds, as.w, bb.w); zd = fmaf(dd, ad.w, bb.w); p = fmaf(zs, zd, p);
    }
    p += __shfl_xor_sync(0xffffffffu, p, 8);
    p += __shfl_xor_sync(0xffffffffu, p, 4);
    p += __shfl_xor_sync(0xffffffffu, p, 2);
    p += __shfl_xor_sync(0xffffffffu, p, 1);
    if (q == 0) out[edge] = p;
}

// ---------------------------------------------------------------------------
extern "C" void kernel_launch(void* const* d_in, const int* in_sizes, int n_in,
                              void* d_out, int out_size) {
    const float* x  = (const float*)d_in[0];   // [n, IN_CH]
    const int*   ei = (const int*)d_in[1];     // [2, e]
    const float* W1 = (const float*)d_in[2];
    const float* b1 = (const float*)d_in[3];
    const float* W2 = (const float*)d_in[4];
    const float* b2 = (const float*)d_in[5];
    float* out = (float*)d_out;                // [e]

    int n = in_sizes[0] / IN_CH;
    int e = in_sizes[1] / 2;
    const int* src = ei;
    const int* dst = ei + e;

    float *p_h, *p_agg1, *p_agg2;
    cudaGetSymbolAddress((void**)&p_h, g_h);
    cudaGetSymbolAddress((void**)&p_agg1, g_agg1);
    cudaGetSymbolAddress((void**)&p_agg2, g_agg2);

    const int T = 256;
    int eg = (e * 16 + T - 1) / T;             // 16 lanes per edge

    init_deg_kernel<<<(n + T - 1) / T, T>>>(n);
    degree_kernel<<<(e + T - 1) / T, T>>>(dst, e);
    dinv_kernel<<<(n + T - 1) / T, T>>>(n);

    // layer 1: h' = (X@W1)*dinv, dual-store (agg1 starts at self-loop term)
    gemm_kernel<IN_CH, false><<<(n + 31) / 32, T>>>(x, W1, nullptr, p_h, p_agg1, n);
    agg_kernel<<<eg, T>>>(src, dst, p_h, p_agg1, e);

    // layer 2: input z1 = relu(dinv*agg1 + b1) fused into GEMM load
    gemm_kernel<HID, true><<<(n + 31) / 32, T>>>(p_agg1, W2, b1, p_h, p_agg2, n);
    agg_kernel<<<eg, T>>>(src, dst, p_h, p_agg2, e);

    // decode with z2 = dinv*agg2 + b2 fused
    decode_kernel<<<eg, T>>>(src, dst, p_agg2, b2, out, e);
}

// round 3
// speedup vs baseline: 1.9822x; 1.4219x over previous
#include <cuda_runtime.h>
#include <math.h>

#define IN_CH 128
#define HID 64
#define NMAX 50000
#define EMAX 800000

// Scratch (__device__ globals; no allocation allowed)
__device__ float g_deg[NMAX];              // degree, then dinv in place
__device__ float g_h[NMAX * HID];          // h' = (X@W) * dinv[row]  (gather source)
__device__ float g_agg1[NMAX * HID];       // layer-1 aggregation (init = h' via dual-store)
__device__ float g_agg2[NMAX * HID];       // layer-2 aggregation

// ---------------------------------------------------------------------------
__global__ void init_deg_kernel(int n) {
    int i = blockIdx.x * blockDim.x + threadIdx.x;
    if (i < n) g_deg[i] = 1.0f;            // self-loop contributes 1
}

__global__ void degree_kernel(const int* __restrict__ dst, int e) {
    int i = blockIdx.x * blockDim.x + threadIdx.x;
    if (i < e) {
        float* p = &g_deg[__ldg(dst + i)];
        asm volatile("red.global.add.f32 [%0], %1;" :: "l"(p), "f"(1.0f) : "memory");
    }
}

__global__ void dinv_kernel(int n) {
    int i = blockIdx.x * blockDim.x + threadIdx.x;
    if (i < n) g_deg[i] = rsqrtf(g_deg[i]);
}

// ---------------------------------------------------------------------------
// GEMM: out[i][c] = dinv[i] * sum_k in[i][k] * W[k][c], dual-stored to H and AGG.
// TRANS: input transform z = relu(dinv[i]*in[i][k] + bIn[k])  (layer-2 input path)
// Block: 256 threads -> 128 nodes x 64 cols. Thread (tx,ty): cols tx*8..+8,
// nodes ty, ty+32, ty+64, ty+96. 16 f32x2 accumulators per thread.
template <int K, bool TRANS>
__global__ void __launch_bounds__(256, 2)
gemm_kernel(const float* __restrict__ X, const float* __restrict__ W,
            const float* __restrict__ bIn,
            float* __restrict__ H, float* __restrict__ AGG, int n) {
    constexpr int XP = K + 4;              // pad: conflict-free Xs reads
    __shared__ float Ws[K * HID];
    __shared__ float Xs[128 * XP];
    const int t = threadIdx.x;
    const int node0 = blockIdx.x * 128;

    // load W [K,HID] coalesced
    for (int i = t * 4; i < K * HID; i += 1024)
        *(float4*)(Ws + i) = *(const float4*)(W + i);

    // load X tile (optionally transformed)
    for (int i = t * 4; i < 128 * K; i += 1024) {
        int r = i / K, c = i % K;          // c multiple of 4
        int node = node0 + r;
        float4 v = make_float4(0.f, 0.f, 0.f, 0.f);
        if (node < n) {
            v = *(const float4*)(X + node * K + c);
            if (TRANS) {
                float di = g_deg[node];
                float4 b = *(const float4*)(bIn + c);
                v.x = fmaxf(fmaf(di, v.x, b.x), 0.f);
                v.y = fmaxf(fmaf(di, v.y, b.y), 0.f);
                v.z = fmaxf(fmaf(di, v.z, b.z), 0.f);
                v.w = fmaxf(fmaf(di, v.w, b.w), 0.f);
            }
        }
        *(float4*)(Xs + r * XP + c) = v;
    }
    __syncthreads();

    const int tx = t & 7;                  // col group
    const int ty = t >> 3;                 // node 0..31 (+32m)
    const int c0 = tx * 8;

    unsigned long long acc[4][4];          // [node m][col pair]: 16 f32x2 accumulators
#pragma unroll
    for (int m = 0; m < 4; ++m)
#pragma unroll
        for (int j = 0; j < 4; ++j) acc[m][j] = 0ULL;

#pragma unroll 4
    for (int k = 0; k < K; ++k) {
        ulonglong2 wA = *(const ulonglong2*)(Ws + k * HID + c0);
        ulonglong2 wB = *(const ulonglong2*)(Ws + k * HID + c0 + 4);
#pragma unroll
        for (int m = 0; m < 4; ++m) {
            float xv = Xs[(ty + 32 * m) * XP + k];
            unsigned long long xx;
            asm("mov.b64 %0, {%1, %1};" : "=l"(xx) : "f"(xv));
            asm("fma.rn.f32x2 %0, %1, %2, %0;" : "+l"(acc[m][0]) : "l"(wA.x), "l"(xx));
            asm("fma.rn.f32x2 %0, %1, %2, %0;" : "+l"(acc[m][1]) : "l"(wA.y), "l"(xx));
            asm("fma.rn.f32x2 %0, %1, %2, %0;" : "+l"(acc[m][2]) : "l"(wB.x), "l"(xx));
            asm("fma.rn.f32x2 %0, %1, %2, %0;" : "+l"(acc[m][3]) : "l"(wB.y), "l"(xx));
        }
    }

#pragma unroll
    for (int m = 0; m < 4; ++m) {
        int node = node0 + ty + 32 * m;
        if (node < n) {
            float di = g_deg[node];
            float o[8];
            asm("mov.b64 {%0,%1}, %2;" : "=f"(o[0]), "=f"(o[1]) : "l"(acc[m][0]));
            asm("mov.b64 {%0,%1}, %2;" : "=f"(o[2]), "=f"(o[3]) : "l"(acc[m][1]));
            asm("mov.b64 {%0,%1}, %2;" : "=f"(o[4]), "=f"(o[5]) : "l"(acc[m][2]));
            asm("mov.b64 {%0,%1}, %2;" : "=f"(o[6]), "=f"(o[7]) : "l"(acc[m][3]));
            float4 r0 = make_float4(o[0] * di, o[1] * di, o[2] * di, o[3] * di);
            float4 r1 = make_float4(o[4] * di, o[5] * di, o[6] * di, o[7] * di);
            int off = node * HID + c0;
            *(float4*)(H + off) = r0;
            *(float4*)(H + off + 4) = r1;
            *(float4*)(AGG + off) = r0;    // self-loop init: agg starts at h'[node]
            *(float4*)(AGG + off + 4) = r1;
        }
    }
}

// ---------------------------------------------------------------------------
// aggregation: agg[dst] += h'[src]  (unweighted; norm folded into producer/consumer)
// 16 lanes per edge, one red.global.add.v4.f32 per lane.
__global__ void agg_kernel(const int* __restrict__ src, const int* __restrict__ dst,
                           const float* __restrict__ h, float* __restrict__ agg, int e) {
    int tid = blockIdx.x * blockDim.x + threadIdx.x;
    int edge = tid >> 4;
    int q = tid & 15;
    if (edge >= e) return;
    int s = __ldg(src + edge);
    int d = __ldg(dst + edge);
    float4 v = *(const float4*)(h + s * HID + q * 4);
    float* p = agg + d * HID + q * 4;
    asm volatile("red.global.add.v4.f32 [%0], {%1,%2,%3,%4};"
                 :: "l"(p), "f"(v.x), "f"(v.y), "f"(v.z), "f"(v.w) : "memory");
}

// ---------------------------------------------------------------------------
// decode: out[e] = dot(z[src], z[dst]), z = dinv*agg2 + b2 applied on the fly.
// 16 lanes per edge, float4 per lane, shfl-xor reduce within the 16-lane group.
__global__ void decode_kernel(const int* __restrict__ src, const int* __restrict__ dst,
                              const float* __restrict__ agg, const float* __restrict__ b,
                              float* __restrict__ out, int e) {
    int tid = blockIdx.x * blockDim.x + threadIdx.x;
    int edge = tid >> 4;
    int q = tid & 15;
    if (edge >= e) return;
    int s = __ldg(src + edge);
    int d = __ldg(dst + edge);
    float ds = g_deg[s], dd = g_deg[d];
    float4 as = *(const float4*)(agg + s * HID + q * 4);
    float4 ad = *(const float4*)(agg + d * HID + q * 4);
    float4 bb = *(const float4*)(b + q * 4);
    float p;
    {
        float zs = fmaf(ds, as.x, bb.x), zd = fmaf(dd, ad.x, bb.x);
        p = zs * zd;
        zs = fmaf(ds, as.y, bb.y); zd = fmaf(dd, ad.y, bb.y); p = fmaf(zs, zd, p);
        zs = fmaf(ds, as.z, bb.z); zd = fmaf(dd, ad.z, bb.z); p = fmaf(zs, zd, p);
        zs = fmaf(ds, as.w, bb.w); zd = fmaf(dd, ad.w, bb.w); p = fmaf(zs, zd, p);
    }
    p += __shfl_xor_sync(0xffffffffu, p, 8);
    p += __shfl_xor_sync(0xffffffffu, p, 4);
    p += __shfl_xor_sync(0xffffffffu, p, 2);
    p += __shfl_xor_sync(0xffffffffu, p, 1);
    if (q == 0) out[edge] = p;
}

// ---------------------------------------------------------------------------
extern "C" void kernel_launch(void* const* d_in, const int* in_sizes, int n_in,
                              void* d_out, int out_size) {
    const float* x  = (const float*)d_in[0];   // [n, IN_CH]
    const int*   ei = (const int*)d_in[1];     // [2, e]
    const float* W1 = (const float*)d_in[2];
    const float* b1 = (const float*)d_in[3];
    const float* W2 = (const float*)d_in[4];
    const float* b2 = (const float*)d_in[5];
    float* out = (float*)d_out;                // [e]

    int n = in_sizes[0] / IN_CH;
    int e = in_sizes[1] / 2;
    const int* src = ei;
    const int* dst = ei + e;

    float *p_h, *p_agg1, *p_agg2;
    cudaGetSymbolAddress((void**)&p_h, g_h);
    cudaGetSymbolAddress((void**)&p_agg1, g_agg1);
    cudaGetSymbolAddress((void**)&p_agg2, g_agg2);

    const int T = 256;
    int eg = (e * 16 + T - 1) / T;             // 16 lanes per edge

    init_deg_kernel<<<(n + T - 1) / T, T>>>(n);
    degree_kernel<<<(e + T - 1) / T, T>>>(dst, e);
    dinv_kernel<<<(n + T - 1) / T, T>>>(n);

    // layer 1: h' = (X@W1)*dinv, dual-store (agg1 starts at self-loop term)
    gemm_kernel<IN_CH, false><<<(n + 127) / 128, T>>>(x, W1, nullptr, p_h, p_agg1, n);
    agg_kernel<<<eg, T>>>(src, dst, p_h, p_agg1, e);

    // layer 2: input z1 = relu(dinv*agg1 + b1) fused into GEMM load
    gemm_kernel<HID, true><<<(n + 127) / 128, T>>>(p_agg1, W2, b1, p_h, p_agg2, n);
    agg_kernel<<<eg, T>>>(src, dst, p_h, p_agg2, e);

    // decode with z2 = dinv*agg2 + b2 fused
    decode_kernel<<<eg, T>>>(src, dst, p_agg2, b2, out, e);
}